// round 5
// baseline (speedup 1.0000x reference)
#include <cuda_runtime.h>
#include <cuda_bf16.h>
#include <cstdint>
#include <math.h>

#define BB 8
#define NSEQ 2048
#define DDIM 512
#define MFLAT (BB*NSEQ)

// ---------------- scratch (device globals: allocation-free) ----------------
__device__ __nv_bfloat16 g_qry_hi[MFLAT*DDIM], g_qry_lo[MFLAT*DDIM];
__device__ __nv_bfloat16 g_ctx_hi[MFLAT*DDIM], g_ctx_lo[MFLAT*DDIM];
__device__ __nv_bfloat16 g_wq_hi[DDIM*DDIM],  g_wq_lo[DDIM*DDIM];
__device__ __nv_bfloat16 g_wv_hi[DDIM*DDIM],  g_wv_lo[DDIM*DDIM];
__device__ __nv_bfloat16 g_wo_hi[DDIM*DDIM],  g_wo_lo[DDIM*DDIM];
__device__ __nv_bfloat16 g_q_hi[MFLAT*DDIM],  g_q_lo[MFLAT*DDIM];
__device__ __nv_bfloat16 g_vT_hi[MFLAT*DDIM], g_vT_lo[MFLAT*DDIM];
__device__ float         g_s[(size_t)BB*NSEQ*NSEQ];
__device__ __nv_bfloat16 g_attn_hi[(size_t)BB*NSEQ*NSEQ], g_attn_lo[(size_t)BB*NSEQ*NSEQ];
__device__ __nv_bfloat16 g_h_hi[MFLAT*DDIM],  g_h_lo[MFLAT*DDIM];

// ---------------- helpers ----------------
__device__ __forceinline__ uint32_t smem_u32(const void* p){
    uint32_t a;
    asm("{ .reg .u64 t; cvta.to.shared.u64 t, %1; cvt.u32.u64 %0, t; }" : "=r"(a) : "l"(p));
    return a;
}
__device__ __forceinline__ void split2(float v, __nv_bfloat16& h, __nv_bfloat16& l){
    h = __float2bfloat16(v);
    l = __float2bfloat16(v - __bfloat162float(h));
}

#define CP_ASYNC16(sm, gm) \
    asm volatile("cp.async.cg.shared.global [%0], [%1], 16;" :: "r"(sm), "l"(gm))
#define CP_COMMIT() asm volatile("cp.async.commit_group;" ::: "memory")
#define CP_WAIT1()  asm volatile("cp.async.wait_group 1;" ::: "memory")
#define CP_WAIT0()  asm volatile("cp.async.wait_group 0;" ::: "memory")

__device__ __forceinline__ void ldmatrix_x4(uint32_t& r0, uint32_t& r1, uint32_t& r2, uint32_t& r3, uint32_t addr){
    asm volatile("ldmatrix.sync.aligned.m8n8.x4.shared.b16 {%0,%1,%2,%3}, [%4];"
        : "=r"(r0), "=r"(r1), "=r"(r2), "=r"(r3) : "r"(addr));
}
__device__ __forceinline__ void mma_bf16(float* c, const uint32_t* a, const uint32_t* b){
    asm volatile(
        "mma.sync.aligned.m16n8k16.row.col.f32.bf16.bf16.f32 "
        "{%0,%1,%2,%3}, {%4,%5,%6,%7}, {%8,%9}, {%0,%1,%2,%3};"
        : "+f"(c[0]), "+f"(c[1]), "+f"(c[2]), "+f"(c[3])
        : "r"(a[0]), "r"(a[1]), "r"(a[2]), "r"(a[3]), "r"(b[0]), "r"(b[1]));
}

// ---------------- HMMA GEMM ----------------
// C[128x128 tile] = alpha * sum over 3 segments of Aseg[M,K] @ Bseg[N,K]^T (+ bias)
// Segments: (Ahi,Bhi), (Ahi,Blo), (Alo,Bhi)  -> split-bf16 fp32 emulation.
// MODE 0: fp32 out. MODE 1: split bf16 out. MODE 2: split bf16 out, transposed
//         per-batch (v^T layout [DDIM, NSEQ]); requires N==DDIM, flat M, z==1.
// BK=64, 3-stage cp.async pipeline, one __syncthreads per K-iteration.
// Smem row pitch 144B (128B data + 16B pad): 144 mod 128 = 16 -> every
// ldmatrix 8-row phase hits distinct 16B offsets mod 128 (conflict-free).
#define PITCH 144
#define TILEB (128*PITCH)          // 18432 B per operand tile
#define STAGEB (2*TILEB)           // A + B
#define NSTAGE 3
#define SMEM_G (NSTAGE*STAGEB)     // 110592 B

template<int MODE>
__global__ __launch_bounds__(256, 1)
void mma_gemm(const __nv_bfloat16* __restrict__ Ahi, const __nv_bfloat16* __restrict__ Alo,
              const __nv_bfloat16* __restrict__ Bhi, const __nv_bfloat16* __restrict__ Blo,
              const float* __restrict__ bias,
              float* __restrict__ outF, __nv_bfloat16* __restrict__ outHi, __nv_bfloat16* __restrict__ outLo,
              int M, int N, int K, float alpha,
              long sA, long sB, long sC)
{
    extern __shared__ __align__(128) char smem[];

    const int tid  = threadIdx.x;
    const int warp = tid >> 5;
    const int lane = tid & 31;
    const int warpM = warp >> 2;   // 0..1  (64 rows each)
    const int warpN = warp & 3;    // 0..3  (32 cols each)

    const int z = blockIdx.z;
    Ahi += (long)z * sA;  Alo += (long)z * sA;
    Bhi += (long)z * sB;  Blo += (long)z * sB;
    if (MODE == 0) { outF += (long)z * sC; }
    else { outHi += (long)z * sC; outLo += (long)z * sC; }

    const int rowBase = blockIdx.y * 128;
    const int colBase = blockIdx.x * 128;

    const uint32_t smBase = smem_u32(smem);

    const __nv_bfloat16* Aseg[3] = {Ahi, Ahi, Alo};
    const __nv_bfloat16* Bseg[3] = {Bhi, Blo, Bhi};
    const int tps = K >> 6;        // 64-k tiles per segment
    const int T = 3 * tps;

    // loader: 2 threads per row, 64B each (4 x cp.async 16B)
    const int ldRow = tid >> 1;
    const int ldOff = (tid & 1) * 64;       // byte offset within 128B of row data

    auto issue = [&](int t){
        const int st = t % NSTAGE;
        const int seg = t / tps;
        const int kk  = (t - seg * tps) << 6;   // element offset
        const __nv_bfloat16* Ap = Aseg[seg] + (long)(rowBase + ldRow) * K + kk + (ldOff >> 1);
        const __nv_bfloat16* Bp = Bseg[seg] + (long)(colBase + ldRow) * K + kk + (ldOff >> 1);
        const uint32_t sa = smBase + st * STAGEB + ldRow * PITCH + ldOff;
        const uint32_t sb = sa + TILEB;
        CP_ASYNC16(sa,      Ap);
        CP_ASYNC16(sa + 16, Ap + 8);
        CP_ASYNC16(sa + 32, Ap + 16);
        CP_ASYNC16(sa + 48, Ap + 24);
        CP_ASYNC16(sb,      Bp);
        CP_ASYNC16(sb + 16, Bp + 8);
        CP_ASYNC16(sb + 32, Bp + 16);
        CP_ASYNC16(sb + 48, Bp + 24);
        CP_COMMIT();
    };

    float acc[4][4][4];
    #pragma unroll
    for (int i = 0; i < 4; i++)
        #pragma unroll
        for (int j = 0; j < 4; j++)
            #pragma unroll
            for (int c = 0; c < 4; c++) acc[i][j][c] = 0.f;

    issue(0);
    issue(1);

    // ldmatrix lane address components (stage-invariant parts)
    const uint32_t aLaneOff = (uint32_t)(warpM*64 + (lane & 15)) * PITCH + ((lane >> 4) & 1) * 16;
    const uint32_t bLaneOff = (uint32_t)(warpN*32 + (lane & 7) + ((lane >> 4) & 1) * 8) * PITCH
                            + ((lane >> 3) & 1) * 16;

    for (int t = 0; t < T; t++) {
        if (t + 1 < T) { CP_WAIT1(); } else { CP_WAIT0(); }
        __syncthreads();
        if (t + 2 < T) issue(t + 2);

        const int st = t % NSTAGE;
        const uint32_t aBase = smBase + st * STAGEB + aLaneOff;
        const uint32_t bBase = smBase + st * STAGEB + TILEB + bLaneOff;

        #pragma unroll
        for (int ks = 0; ks < 4; ks++) {
            const uint32_t kByte = ks * 32;
            uint32_t afr[4][4];
            #pragma unroll
            for (int mt = 0; mt < 4; mt++)
                ldmatrix_x4(afr[mt][0], afr[mt][1], afr[mt][2], afr[mt][3],
                            aBase + mt * 16 * PITCH + kByte);
            uint32_t bfr[2][4];   // [pair][m0..m3]: nt=2p -> {m0,m1}, nt=2p+1 -> {m2,m3}
            #pragma unroll
            for (int p = 0; p < 2; p++)
                ldmatrix_x4(bfr[p][0], bfr[p][1], bfr[p][2], bfr[p][3],
                            bBase + p * 16 * PITCH + kByte);
            #pragma unroll
            for (int mt = 0; mt < 4; mt++)
                #pragma unroll
                for (int nt = 0; nt < 4; nt++)
                    mma_bf16(acc[mt][nt], afr[mt], &bfr[nt >> 1][(nt & 1) * 2]);
        }
    }

    // ---------------- epilogue (registers -> gmem) ----------------
    #pragma unroll
    for (int mt = 0; mt < 4; mt++) {
        const int r0 = rowBase + warpM*64 + mt*16 + (lane >> 2);
        #pragma unroll
        for (int nt = 0; nt < 4; nt++) {
            const int gc = colBase + warpN*32 + nt*8 + (lane & 3)*2;
            float v00 = acc[mt][nt][0] * alpha;
            float v01 = acc[mt][nt][1] * alpha;
            float v10 = acc[mt][nt][2] * alpha;
            float v11 = acc[mt][nt][3] * alpha;
            if (bias) {
                const float b0 = bias[gc], b1 = bias[gc+1];
                v00 += b0; v01 += b1; v10 += b0; v11 += b1;
            }
            if (MODE == 0) {
                *(float2*)&outF[(long)r0 * N + gc]       = make_float2(v00, v01);
                *(float2*)&outF[(long)(r0+8) * N + gc]   = make_float2(v10, v11);
            } else if (MODE == 1) {
                __nv_bfloat162 h, l;
                split2(v00, h.x, l.x); split2(v01, h.y, l.y);
                *(__nv_bfloat162*)&outHi[(long)r0 * N + gc] = h;
                *(__nv_bfloat162*)&outLo[(long)r0 * N + gc] = l;
                split2(v10, h.x, l.x); split2(v11, h.y, l.y);
                *(__nv_bfloat162*)&outHi[(long)(r0+8) * N + gc] = h;
                *(__nv_bfloat162*)&outLo[(long)(r0+8) * N + gc] = l;
            } else { // MODE 2: v^T per batch [DDIM, NSEQ]
                const int rows[2] = {r0, r0 + 8};
                const float vals[2][2] = {{v00, v01}, {v10, v11}};
                #pragma unroll
                for (int rr = 0; rr < 2; rr++) {
                    const int bb = rows[rr] >> 11, tok = rows[rr] & 2047;
                    const long base = (long)bb * (DDIM * NSEQ) + tok;
                    #pragma unroll
                    for (int cc = 0; cc < 2; cc++) {
                        __nv_bfloat16 h, l; split2(vals[rr][cc], h, l);
                        const long idx = base + (long)(gc + cc) * NSEQ;
                        outHi[idx] = h;
                        outLo[idx] = l;
                    }
                }
            }
        }
    }
}

// ---------------- fp32 -> (bf16 hi, bf16 lo) ----------------
__global__ __launch_bounds__(256)
void split_kernel(const float* __restrict__ x, __nv_bfloat16* __restrict__ hi,
                  __nv_bfloat16* __restrict__ lo, int n4)
{
    const int i = blockIdx.x * blockDim.x + threadIdx.x;
    if (i >= n4) return;
    float4 v = ((const float4*)x)[i];
    __nv_bfloat162 h0, h1, l0, l1;
    split2(v.x, h0.x, l0.x); split2(v.y, h0.y, l0.y);
    split2(v.z, h1.x, l1.x); split2(v.w, h1.y, l1.y);
    ((__nv_bfloat162*)hi)[2*i]   = h0;
    ((__nv_bfloat162*)hi)[2*i+1] = h1;
    ((__nv_bfloat162*)lo)[2*i]   = l0;
    ((__nv_bfloat162*)lo)[2*i+1] = l1;
}

// ---------------- softmax + split (register-resident row, n=2048) ----------------
__global__ __launch_bounds__(256)
void softmax_split_kernel(const float* __restrict__ s, __nv_bfloat16* __restrict__ hi,
                          __nv_bfloat16* __restrict__ lo)
{
    const long rbase = (long)blockIdx.x * NSEQ;
    const float* row = s + rbase;
    const int tid = threadIdx.x;
    const int warp = tid >> 5, lane = tid & 31;
    __shared__ float red[8];

    // load 8 floats/thread (2 x float4, coalesced)
    float4 x0 = ((const float4*)row)[tid];
    float4 x1 = ((const float4*)row)[tid + 256];

    float m = fmaxf(fmaxf(fmaxf(x0.x, x0.y), fmaxf(x0.z, x0.w)),
                    fmaxf(fmaxf(x1.x, x1.y), fmaxf(x1.z, x1.w)));
    #pragma unroll
    for (int o = 16; o > 0; o >>= 1) m = fmaxf(m, __shfl_xor_sync(0xFFFFFFFF, m, o));
    if (lane == 0) red[warp] = m;
    __syncthreads();
    m = red[lane & 7];
    #pragma unroll
    for (int o = 4; o > 0; o >>= 1) m = fmaxf(m, __shfl_xor_sync(0xFFFFFFFF, m, o));

    x0.x = __expf(x0.x - m); x0.y = __expf(x0.y - m);
    x0.z = __expf(x0.z - m); x0.w = __expf(x0.w - m);
    x1.x = __expf(x1.x - m); x1.y = __expf(x1.y - m);
    x1.z = __expf(x1.z - m); x1.w = __expf(x1.w - m);

    float sum = (x0.x + x0.y) + (x0.z + x0.w) + (x1.x + x1.y) + (x1.z + x1.w);
    #pragma unroll
    for (int o = 16; o > 0; o >>= 1) sum += __shfl_xor_sync(0xFFFFFFFF, sum, o);
    __syncthreads();
    if (lane == 0) red[warp] = sum;
    __syncthreads();
    sum = red[lane & 7];
    #pragma unroll
    for (int o = 4; o > 0; o >>= 1) sum += __shfl_xor_sync(0xFFFFFFFF, sum, o);
    const float inv = 1.f / sum;

    // write hi/lo packed (4 bf16 = 8B per store)
    __nv_bfloat162 h[4], l[4];
    split2(x0.x * inv, h[0].x, l[0].x); split2(x0.y * inv, h[0].y, l[0].y);
    split2(x0.z * inv, h[1].x, l[1].x); split2(x0.w * inv, h[1].y, l[1].y);
    split2(x1.x * inv, h[2].x, l[2].x); split2(x1.y * inv, h[2].y, l[2].y);
    split2(x1.z * inv, h[3].x, l[3].x); split2(x1.w * inv, h[3].y, l[3].y);

    uint2* hp = (uint2*)(hi + rbase);
    uint2* lp = (uint2*)(lo + rbase);
    uint2 hv0, lv0, hv1, lv1;
    hv0.x = *(uint32_t*)&h[0]; hv0.y = *(uint32_t*)&h[1];
    hv1.x = *(uint32_t*)&h[2]; hv1.y = *(uint32_t*)&h[3];
    lv0.x = *(uint32_t*)&l[0]; lv0.y = *(uint32_t*)&l[1];
    lv1.x = *(uint32_t*)&l[2]; lv1.y = *(uint32_t*)&l[3];
    hp[tid] = hv0; hp[tid + 256] = hv1;
    lp[tid] = lv0; lp[tid + 256] = lv1;
}

// ---------------- launch ----------------
extern "C" void kernel_launch(void* const* d_in, const int* in_sizes, int n_in,
                              void* d_out, int out_size)
{
    (void)in_sizes; (void)n_in; (void)out_size;
    const float* query   = (const float*)d_in[0];
    const float* context = (const float*)d_in[1];
    const float* Wq      = (const float*)d_in[2];
    const float* bq      = (const float*)d_in[3];
    const float* Wv      = (const float*)d_in[4];
    const float* bv      = (const float*)d_in[5];
    const float* Wo      = (const float*)d_in[6];
    const float* bo      = (const float*)d_in[7];
    float* out = (float*)d_out;

    __nv_bfloat16 *qry_hi,*qry_lo,*ctx_hi,*ctx_lo,*wq_hi,*wq_lo,*wv_hi,*wv_lo,*wo_hi,*wo_lo;
    __nv_bfloat16 *q_hi,*q_lo,*vT_hi,*vT_lo,*attn_hi,*attn_lo,*h_hi,*h_lo;
    float* s;
    cudaGetSymbolAddress((void**)&qry_hi, g_qry_hi);  cudaGetSymbolAddress((void**)&qry_lo, g_qry_lo);
    cudaGetSymbolAddress((void**)&ctx_hi, g_ctx_hi);  cudaGetSymbolAddress((void**)&ctx_lo, g_ctx_lo);
    cudaGetSymbolAddress((void**)&wq_hi,  g_wq_hi);   cudaGetSymbolAddress((void**)&wq_lo,  g_wq_lo);
    cudaGetSymbolAddress((void**)&wv_hi,  g_wv_hi);   cudaGetSymbolAddress((void**)&wv_lo,  g_wv_lo);
    cudaGetSymbolAddress((void**)&wo_hi,  g_wo_hi);   cudaGetSymbolAddress((void**)&wo_lo,  g_wo_lo);
    cudaGetSymbolAddress((void**)&q_hi,   g_q_hi);    cudaGetSymbolAddress((void**)&q_lo,   g_q_lo);
    cudaGetSymbolAddress((void**)&vT_hi,  g_vT_hi);   cudaGetSymbolAddress((void**)&vT_lo,  g_vT_lo);
    cudaGetSymbolAddress((void**)&attn_hi,g_attn_hi); cudaGetSymbolAddress((void**)&attn_lo,g_attn_lo);
    cudaGetSymbolAddress((void**)&h_hi,   g_h_hi);    cudaGetSymbolAddress((void**)&h_lo,   g_h_lo);
    cudaGetSymbolAddress((void**)&s,      g_s);

    cudaFuncSetAttribute(mma_gemm<0>, cudaFuncAttributeMaxDynamicSharedMemorySize, SMEM_G);
    cudaFuncSetAttribute(mma_gemm<1>, cudaFuncAttributeMaxDynamicSharedMemorySize, SMEM_G);
    cudaFuncSetAttribute(mma_gemm<2>, cudaFuncAttributeMaxDynamicSharedMemorySize, SMEM_G);

    const float scale = 1.0f / sqrtf((float)DDIM);

    // split inputs
    {
        int n4 = (MFLAT * DDIM) / 4;
        split_kernel<<<(n4 + 255) / 256, 256>>>(query,   qry_hi, qry_lo, n4);
        split_kernel<<<(n4 + 255) / 256, 256>>>(context, ctx_hi, ctx_lo, n4);
        int w4 = (DDIM * DDIM) / 4;
        split_kernel<<<(w4 + 255) / 256, 256>>>(Wq, wq_hi, wq_lo, w4);
        split_kernel<<<(w4 + 255) / 256, 256>>>(Wv, wv_hi, wv_lo, w4);
        split_kernel<<<(w4 + 255) / 256, 256>>>(Wo, wo_hi, wo_lo, w4);
    }

    // 1) q = query @ Wq^T + bq  -> split q
    mma_gemm<1><<<dim3(DDIM/128, MFLAT/128, 1), 256, SMEM_G>>>(
        qry_hi, qry_lo, wq_hi, wq_lo, bq, nullptr, q_hi, q_lo,
        MFLAT, DDIM, DDIM, 1.0f, 0, 0, 0);

    // 2) v = context @ Wv^T + bv -> split v^T (per batch [DDIM, NSEQ])
    mma_gemm<2><<<dim3(DDIM/128, MFLAT/128, 1), 256, SMEM_G>>>(
        ctx_hi, ctx_lo, wv_hi, wv_lo, bv, nullptr, vT_hi, vT_lo,
        MFLAT, DDIM, DDIM, 1.0f, 0, 0, 0);

    // 3) scores = scale * q @ context^T  (batched) -> fp32 s
    mma_gemm<0><<<dim3(NSEQ/128, NSEQ/128, BB), 256, SMEM_G>>>(
        q_hi, q_lo, ctx_hi, ctx_lo, nullptr, s, nullptr, nullptr,
        NSEQ, NSEQ, DDIM, scale,
        (long)NSEQ * DDIM, (long)NSEQ * DDIM, (long)NSEQ * NSEQ);

    // 4) softmax rows -> split attn
    softmax_split_kernel<<<BB * NSEQ, 256>>>(s, attn_hi, attn_lo);

    // 5) h = attn @ v = attn @ (v^T)^T  (batched) -> split h
    mma_gemm<1><<<dim3(DDIM/128, NSEQ/128, BB), 256, SMEM_G>>>(
        attn_hi, attn_lo, vT_hi, vT_lo, nullptr, nullptr, h_hi, h_lo,
        NSEQ, DDIM, NSEQ, 1.0f,
        (long)NSEQ * NSEQ, (long)DDIM * NSEQ, (long)NSEQ * DDIM);

    // 6) out = h @ Wo^T + bo -> fp32
    mma_gemm<0><<<dim3(DDIM/128, MFLAT/128, 1), 256, SMEM_G>>>(
        h_hi, h_lo, wo_hi, wo_lo, bo, out, nullptr, nullptr,
        MFLAT, DDIM, DDIM, 1.0f, 0, 0, 0);
}

// round 6
// speedup vs baseline: 1.2880x; 1.2880x over previous
#include <cuda_runtime.h>
#include <cuda_bf16.h>
#include <cstdint>
#include <math.h>

#define BB 8
#define NSEQ 2048
#define DDIM 512
#define MFLAT (BB*NSEQ)

// ---------------- scratch (device globals: allocation-free) ----------------
__device__ __nv_bfloat16 g_qry_hi[MFLAT*DDIM], g_qry_lo[MFLAT*DDIM];
__device__ __nv_bfloat16 g_ctx_hi[MFLAT*DDIM], g_ctx_lo[MFLAT*DDIM];
__device__ __nv_bfloat16 g_wq_hi[DDIM*DDIM],  g_wq_lo[DDIM*DDIM];
__device__ __nv_bfloat16 g_wv_hi[DDIM*DDIM],  g_wv_lo[DDIM*DDIM];
__device__ __nv_bfloat16 g_wo_hi[DDIM*DDIM],  g_wo_lo[DDIM*DDIM];
__device__ __nv_bfloat16 g_q_hi[MFLAT*DDIM],  g_q_lo[MFLAT*DDIM];
__device__ __nv_bfloat16 g_vT_hi[MFLAT*DDIM], g_vT_lo[MFLAT*DDIM];
__device__ float         g_s[(size_t)BB*NSEQ*NSEQ];
__device__ __nv_bfloat16 g_attn_hi[(size_t)BB*NSEQ*NSEQ], g_attn_lo[(size_t)BB*NSEQ*NSEQ];
__device__ __nv_bfloat16 g_h_hi[MFLAT*DDIM],  g_h_lo[MFLAT*DDIM];

// ---------------- helpers ----------------
__device__ __forceinline__ uint32_t smem_u32(const void* p){
    uint32_t a;
    asm("{ .reg .u64 t; cvta.to.shared.u64 t, %1; cvt.u32.u64 %0, t; }" : "=r"(a) : "l"(p));
    return a;
}
__device__ __forceinline__ void split2(float v, __nv_bfloat16& h, __nv_bfloat16& l){
    h = __float2bfloat16(v);
    l = __float2bfloat16(v - __bfloat162float(h));
}

#define CP_ASYNC16(sm, gm) \
    asm volatile("cp.async.cg.shared.global [%0], [%1], 16;" :: "r"(sm), "l"(gm))
#define CP_COMMIT() asm volatile("cp.async.commit_group;" ::: "memory")
#define CP_WAIT1()  asm volatile("cp.async.wait_group 1;" ::: "memory")
#define CP_WAIT0()  asm volatile("cp.async.wait_group 0;" ::: "memory")

__device__ __forceinline__ void ldmatrix_x4(uint32_t& r0, uint32_t& r1, uint32_t& r2, uint32_t& r3, uint32_t addr){
    asm volatile("ldmatrix.sync.aligned.m8n8.x4.shared.b16 {%0,%1,%2,%3}, [%4];"
        : "=r"(r0), "=r"(r1), "=r"(r2), "=r"(r3) : "r"(addr));
}
__device__ __forceinline__ void mma_bf16(float* c, const uint32_t* a, const uint32_t* b){
    asm volatile(
        "mma.sync.aligned.m16n8k16.row.col.f32.bf16.bf16.f32 "
        "{%0,%1,%2,%3}, {%4,%5,%6,%7}, {%8,%9}, {%0,%1,%2,%3};"
        : "+f"(c[0]), "+f"(c[1]), "+f"(c[2]), "+f"(c[3])
        : "r"(a[0]), "r"(a[1]), "r"(a[2]), "r"(a[3]), "r"(b[0]), "r"(b[1]));
}

// ---------------- HMMA GEMM ----------------
// C[128x128 tile] = alpha * sum over 3 segments of Aseg[M,K] @ Bseg[N,K]^T (+ bias)
// Segments: (Ahi,Bhi), (Ahi,Blo), (Alo,Bhi)  -> split-bf16 fp32 emulation.
// MODE 0: fp32 out. MODE 1: split bf16 out. MODE 2: split bf16 out, transposed
//         per-batch (v^T layout [DDIM, NSEQ]); requires N==DDIM, flat M, z==1.
// BK=32, 3-stage cp.async pipeline, ONE __syncthreads per iteration,
// 60 KB dynamic smem -> 2 CTAs/SM. Row pitch 80B: conflict-free ldmatrix.
#define PITCH 80
#define TILEB (128*PITCH)          // 10240 B per operand tile
#define STAGEB (2*TILEB)           // A + B = 20480 B
#define NSTAGE 3
#define SMEM_G (NSTAGE*STAGEB)     // 61440 B

template<int MODE>
__global__ __launch_bounds__(256, 2)
void mma_gemm(const __nv_bfloat16* __restrict__ Ahi, const __nv_bfloat16* __restrict__ Alo,
              const __nv_bfloat16* __restrict__ Bhi, const __nv_bfloat16* __restrict__ Blo,
              const float* __restrict__ bias,
              float* __restrict__ outF, __nv_bfloat16* __restrict__ outHi, __nv_bfloat16* __restrict__ outLo,
              int M, int N, int K, float alpha,
              long sA, long sB, long sC)
{
    extern __shared__ __align__(128) char smem[];

    const int tid  = threadIdx.x;
    const int warp = tid >> 5;
    const int lane = tid & 31;
    const int warpM = warp >> 2;   // 0..1  (64 rows each)
    const int warpN = warp & 3;    // 0..3  (32 cols each)

    const int z = blockIdx.z;
    Ahi += (long)z * sA;  Alo += (long)z * sA;
    Bhi += (long)z * sB;  Blo += (long)z * sB;
    if (MODE == 0) { outF += (long)z * sC; }
    else { outHi += (long)z * sC; outLo += (long)z * sC; }

    const int rowBase = blockIdx.y * 128;
    const int colBase = blockIdx.x * 128;

    const uint32_t smBase = smem_u32(smem);

    const __nv_bfloat16* Aseg[3] = {Ahi, Ahi, Alo};
    const __nv_bfloat16* Bseg[3] = {Bhi, Blo, Bhi};
    const int tps = K >> 5;        // 32-k tiles per segment
    const int T = 3 * tps;

    // loader: 2 threads per row, 32B each (2 x cp.async 16B)
    const int ldRow = tid >> 1;
    const int ldOff = (tid & 1) * 32;   // byte offset within 64B row data

    auto issue = [&](int t){
        const int st = t % NSTAGE;
        const int seg = t / tps;
        const int kk  = (t - seg * tps) << 5;   // element offset
        const __nv_bfloat16* Ap = Aseg[seg] + (long)(rowBase + ldRow) * K + kk + (ldOff >> 1);
        const __nv_bfloat16* Bp = Bseg[seg] + (long)(colBase + ldRow) * K + kk + (ldOff >> 1);
        const uint32_t sa = smBase + st * STAGEB + ldRow * PITCH + ldOff;
        const uint32_t sb = sa + TILEB;
        CP_ASYNC16(sa,      Ap);
        CP_ASYNC16(sa + 16, Ap + 8);
        CP_ASYNC16(sb,      Bp);
        CP_ASYNC16(sb + 16, Bp + 8);
        CP_COMMIT();
    };

    float acc[4][4][4];
    #pragma unroll
    for (int i = 0; i < 4; i++)
        #pragma unroll
        for (int j = 0; j < 4; j++)
            #pragma unroll
            for (int c = 0; c < 4; c++) acc[i][j][c] = 0.f;

    issue(0);
    issue(1);

    // ldmatrix lane address components (stage-invariant parts)
    const uint32_t aLaneOff = (uint32_t)(warpM*64 + (lane & 15)) * PITCH + ((lane >> 4) & 1) * 16;
    const uint32_t bLaneOff = (uint32_t)(warpN*32 + (lane & 7) + ((lane >> 4) & 1) * 8) * PITCH
                            + ((lane >> 3) & 1) * 16;

    for (int t = 0; t < T; t++) {
        if (t + 1 < T) { CP_WAIT1(); } else { CP_WAIT0(); }
        __syncthreads();
        if (t + 2 < T) issue(t + 2);

        const int st = t % NSTAGE;
        const uint32_t aBase = smBase + st * STAGEB + aLaneOff;
        const uint32_t bBase = smBase + st * STAGEB + TILEB + bLaneOff;

        #pragma unroll
        for (int ks = 0; ks < 2; ks++) {
            const uint32_t kByte = ks * 32;
            uint32_t afr[4][4];
            #pragma unroll
            for (int mt = 0; mt < 4; mt++)
                ldmatrix_x4(afr[mt][0], afr[mt][1], afr[mt][2], afr[mt][3],
                            aBase + mt * 16 * PITCH + kByte);
            uint32_t bfr[2][4];   // [pair][..]: nt=2p -> regs {0,1}, nt=2p+1 -> regs {2,3}
            #pragma unroll
            for (int p = 0; p < 2; p++)
                ldmatrix_x4(bfr[p][0], bfr[p][1], bfr[p][2], bfr[p][3],
                            bBase + p * 16 * PITCH + kByte);
            #pragma unroll
            for (int mt = 0; mt < 4; mt++)
                #pragma unroll
                for (int nt = 0; nt < 4; nt++)
                    mma_bf16(acc[mt][nt], afr[mt], &bfr[nt >> 1][(nt & 1) * 2]);
        }
    }

    // ---------------- epilogue (registers -> gmem) ----------------
    #pragma unroll
    for (int mt = 0; mt < 4; mt++) {
        const int r0 = rowBase + warpM*64 + mt*16 + (lane >> 2);
        #pragma unroll
        for (int nt = 0; nt < 4; nt++) {
            const int gc = colBase + warpN*32 + nt*8 + (lane & 3)*2;
            float v00 = acc[mt][nt][0] * alpha;
            float v01 = acc[mt][nt][1] * alpha;
            float v10 = acc[mt][nt][2] * alpha;
            float v11 = acc[mt][nt][3] * alpha;
            if (bias) {
                const float b0 = bias[gc], b1 = bias[gc+1];
                v00 += b0; v01 += b1; v10 += b0; v11 += b1;
            }
            if (MODE == 0) {
                *(float2*)&outF[(long)r0 * N + gc]       = make_float2(v00, v01);
                *(float2*)&outF[(long)(r0+8) * N + gc]   = make_float2(v10, v11);
            } else if (MODE == 1) {
                __nv_bfloat162 h, l;
                split2(v00, h.x, l.x); split2(v01, h.y, l.y);
                *(__nv_bfloat162*)&outHi[(long)r0 * N + gc] = h;
                *(__nv_bfloat162*)&outLo[(long)r0 * N + gc] = l;
                split2(v10, h.x, l.x); split2(v11, h.y, l.y);
                *(__nv_bfloat162*)&outHi[(long)(r0+8) * N + gc] = h;
                *(__nv_bfloat162*)&outLo[(long)(r0+8) * N + gc] = l;
            } else { // MODE 2: v^T per batch [DDIM, NSEQ]
                const int rows[2] = {r0, r0 + 8};
                const float vals[2][2] = {{v00, v01}, {v10, v11}};
                #pragma unroll
                for (int rr = 0; rr < 2; rr++) {
                    const int bb = rows[rr] >> 11, tok = rows[rr] & 2047;
                    const long base = (long)bb * (DDIM * NSEQ) + tok;
                    #pragma unroll
                    for (int cc = 0; cc < 2; cc++) {
                        __nv_bfloat16 h, l; split2(vals[rr][cc], h, l);
                        const long idx = base + (long)(gc + cc) * NSEQ;
                        outHi[idx] = h;
                        outLo[idx] = l;
                    }
                }
            }
        }
    }
}

// ---------------- fp32 -> (bf16 hi, bf16 lo) ----------------
__global__ __launch_bounds__(256)
void split_kernel(const float* __restrict__ x, __nv_bfloat16* __restrict__ hi,
                  __nv_bfloat16* __restrict__ lo, int n4)
{
    const int i = blockIdx.x * blockDim.x + threadIdx.x;
    if (i >= n4) return;
    float4 v = ((const float4*)x)[i];
    __nv_bfloat162 h0, h1, l0, l1;
    split2(v.x, h0.x, l0.x); split2(v.y, h0.y, l0.y);
    split2(v.z, h1.x, l1.x); split2(v.w, h1.y, l1.y);
    ((__nv_bfloat162*)hi)[2*i]   = h0;
    ((__nv_bfloat162*)hi)[2*i+1] = h1;
    ((__nv_bfloat162*)lo)[2*i]   = l0;
    ((__nv_bfloat162*)lo)[2*i+1] = l1;
}

// ---------------- softmax + split (register-resident row, n=2048) ----------------
__global__ __launch_bounds__(256)
void softmax_split_kernel(const float* __restrict__ s, __nv_bfloat16* __restrict__ hi,
                          __nv_bfloat16* __restrict__ lo)
{
    const long rbase = (long)blockIdx.x * NSEQ;
    const float* row = s + rbase;
    const int tid = threadIdx.x;
    const int warp = tid >> 5, lane = tid & 31;
    __shared__ float red[8];

    float4 x0 = ((const float4*)row)[tid];
    float4 x1 = ((const float4*)row)[tid + 256];

    float m = fmaxf(fmaxf(fmaxf(x0.x, x0.y), fmaxf(x0.z, x0.w)),
                    fmaxf(fmaxf(x1.x, x1.y), fmaxf(x1.z, x1.w)));
    #pragma unroll
    for (int o = 16; o > 0; o >>= 1) m = fmaxf(m, __shfl_xor_sync(0xFFFFFFFF, m, o));
    if (lane == 0) red[warp] = m;
    __syncthreads();
    m = red[lane & 7];
    #pragma unroll
    for (int o = 4; o > 0; o >>= 1) m = fmaxf(m, __shfl_xor_sync(0xFFFFFFFF, m, o));

    x0.x = __expf(x0.x - m); x0.y = __expf(x0.y - m);
    x0.z = __expf(x0.z - m); x0.w = __expf(x0.w - m);
    x1.x = __expf(x1.x - m); x1.y = __expf(x1.y - m);
    x1.z = __expf(x1.z - m); x1.w = __expf(x1.w - m);

    float sum = (x0.x + x0.y) + (x0.z + x0.w) + (x1.x + x1.y) + (x1.z + x1.w);
    #pragma unroll
    for (int o = 16; o > 0; o >>= 1) sum += __shfl_xor_sync(0xFFFFFFFF, sum, o);
    __syncthreads();
    if (lane == 0) red[warp] = sum;
    __syncthreads();
    sum = red[lane & 7];
    #pragma unroll
    for (int o = 4; o > 0; o >>= 1) sum += __shfl_xor_sync(0xFFFFFFFF, sum, o);
    const float inv = 1.f / sum;

    __nv_bfloat162 h[4], l[4];
    split2(x0.x * inv, h[0].x, l[0].x); split2(x0.y * inv, h[0].y, l[0].y);
    split2(x0.z * inv, h[1].x, l[1].x); split2(x0.w * inv, h[1].y, l[1].y);
    split2(x1.x * inv, h[2].x, l[2].x); split2(x1.y * inv, h[2].y, l[2].y);
    split2(x1.z * inv, h[3].x, l[3].x); split2(x1.w * inv, h[3].y, l[3].y);

    uint2* hp = (uint2*)(hi + rbase);
    uint2* lp = (uint2*)(lo + rbase);
    uint2 hv0, lv0, hv1, lv1;
    hv0.x = *(uint32_t*)&h[0]; hv0.y = *(uint32_t*)&h[1];
    hv1.x = *(uint32_t*)&h[2]; hv1.y = *(uint32_t*)&h[3];
    lv0.x = *(uint32_t*)&l[0]; lv0.y = *(uint32_t*)&l[1];
    lv1.x = *(uint32_t*)&l[2]; lv1.y = *(uint32_t*)&l[3];
    hp[tid] = hv0; hp[tid + 256] = hv1;
    lp[tid] = lv0; lp[tid + 256] = lv1;
}

// ---------------- launch ----------------
extern "C" void kernel_launch(void* const* d_in, const int* in_sizes, int n_in,
                              void* d_out, int out_size)
{
    (void)in_sizes; (void)n_in; (void)out_size;
    const float* query   = (const float*)d_in[0];
    const float* context = (const float*)d_in[1];
    const float* Wq      = (const float*)d_in[2];
    const float* bq      = (const float*)d_in[3];
    const float* Wv      = (const float*)d_in[4];
    const float* bv      = (const float*)d_in[5];
    const float* Wo      = (const float*)d_in[6];
    const float* bo      = (const float*)d_in[7];
    float* out = (float*)d_out;

    __nv_bfloat16 *qry_hi,*qry_lo,*ctx_hi,*ctx_lo,*wq_hi,*wq_lo,*wv_hi,*wv_lo,*wo_hi,*wo_lo;
    __nv_bfloat16 *q_hi,*q_lo,*vT_hi,*vT_lo,*attn_hi,*attn_lo,*h_hi,*h_lo;
    float* s;
    cudaGetSymbolAddress((void**)&qry_hi, g_qry_hi);  cudaGetSymbolAddress((void**)&qry_lo, g_qry_lo);
    cudaGetSymbolAddress((void**)&ctx_hi, g_ctx_hi);  cudaGetSymbolAddress((void**)&ctx_lo, g_ctx_lo);
    cudaGetSymbolAddress((void**)&wq_hi,  g_wq_hi);   cudaGetSymbolAddress((void**)&wq_lo,  g_wq_lo);
    cudaGetSymbolAddress((void**)&wv_hi,  g_wv_hi);   cudaGetSymbolAddress((void**)&wv_lo,  g_wv_lo);
    cudaGetSymbolAddress((void**)&wo_hi,  g_wo_hi);   cudaGetSymbolAddress((void**)&wo_lo,  g_wo_lo);
    cudaGetSymbolAddress((void**)&q_hi,   g_q_hi);    cudaGetSymbolAddress((void**)&q_lo,   g_q_lo);
    cudaGetSymbolAddress((void**)&vT_hi,  g_vT_hi);   cudaGetSymbolAddress((void**)&vT_lo,  g_vT_lo);
    cudaGetSymbolAddress((void**)&attn_hi,g_attn_hi); cudaGetSymbolAddress((void**)&attn_lo,g_attn_lo);
    cudaGetSymbolAddress((void**)&h_hi,   g_h_hi);    cudaGetSymbolAddress((void**)&h_lo,   g_h_lo);
    cudaGetSymbolAddress((void**)&s,      g_s);

    cudaFuncSetAttribute(mma_gemm<0>, cudaFuncAttributeMaxDynamicSharedMemorySize, SMEM_G);
    cudaFuncSetAttribute(mma_gemm<1>, cudaFuncAttributeMaxDynamicSharedMemorySize, SMEM_G);
    cudaFuncSetAttribute(mma_gemm<2>, cudaFuncAttributeMaxDynamicSharedMemorySize, SMEM_G);

    const float scale = 1.0f / sqrtf((float)DDIM);

    // split inputs
    {
        int n4 = (MFLAT * DDIM) / 4;
        split_kernel<<<(n4 + 255) / 256, 256>>>(query,   qry_hi, qry_lo, n4);
        split_kernel<<<(n4 + 255) / 256, 256>>>(context, ctx_hi, ctx_lo, n4);
        int w4 = (DDIM * DDIM) / 4;
        split_kernel<<<(w4 + 255) / 256, 256>>>(Wq, wq_hi, wq_lo, w4);
        split_kernel<<<(w4 + 255) / 256, 256>>>(Wv, wv_hi, wv_lo, w4);
        split_kernel<<<(w4 + 255) / 256, 256>>>(Wo, wo_hi, wo_lo, w4);
    }

    // 1) q = query @ Wq^T + bq  -> split q
    mma_gemm<1><<<dim3(DDIM/128, MFLAT/128, 1), 256, SMEM_G>>>(
        qry_hi, qry_lo, wq_hi, wq_lo, bq, nullptr, q_hi, q_lo,
        MFLAT, DDIM, DDIM, 1.0f, 0, 0, 0);

    // 2) v = context @ Wv^T + bv -> split v^T (per batch [DDIM, NSEQ])
    mma_gemm<2><<<dim3(DDIM/128, MFLAT/128, 1), 256, SMEM_G>>>(
        ctx_hi, ctx_lo, wv_hi, wv_lo, bv, nullptr, vT_hi, vT_lo,
        MFLAT, DDIM, DDIM, 1.0f, 0, 0, 0);

    // 3) scores = scale * q @ context^T  (batched) -> fp32 s
    mma_gemm<0><<<dim3(NSEQ/128, NSEQ/128, BB), 256, SMEM_G>>>(
        q_hi, q_lo, ctx_hi, ctx_lo, nullptr, s, nullptr, nullptr,
        NSEQ, NSEQ, DDIM, scale,
        (long)NSEQ * DDIM, (long)NSEQ * DDIM, (long)NSEQ * NSEQ);

    // 4) softmax rows -> split attn
    softmax_split_kernel<<<BB * NSEQ, 256>>>(s, attn_hi, attn_lo);

    // 5) h = attn @ v = attn @ (v^T)^T  (batched) -> split h
    mma_gemm<1><<<dim3(DDIM/128, NSEQ/128, BB), 256, SMEM_G>>>(
        attn_hi, attn_lo, vT_hi, vT_lo, nullptr, nullptr, h_hi, h_lo,
        NSEQ, DDIM, NSEQ, 1.0f,
        (long)NSEQ * NSEQ, (long)DDIM * NSEQ, (long)NSEQ * DDIM);

    // 6) out = h @ Wo^T + bo -> fp32
    mma_gemm<0><<<dim3(DDIM/128, MFLAT/128, 1), 256, SMEM_G>>>(
        h_hi, h_lo, wo_hi, wo_lo, bo, out, nullptr, nullptr,
        MFLAT, DDIM, DDIM, 1.0f, 0, 0, 0);
}